// round 3
// baseline (speedup 1.0000x reference)
#include <cuda_runtime.h>
#include <math.h>

#define NQ   16384   // B*N1
#define N1_  4096
#define N2_  1024
#define DS   128
#define DD   64
#define DCAT 192
#define DOUT 256
#define KI   8
#define KN   16

// ---------------- scratch (device globals; no allocation allowed) ----------------
__device__ float g_xe [NQ*DS];
__device__ float g_x2i[NQ*DS];
__device__ float g_A  [NQ*DS];
__device__ float g_Dm [NQ*DS];
__device__ float g_VX [NQ*DS];
__device__ float g_agg[NQ*DS];
__device__ float g_cat[NQ*DCAT];
__device__ float g_WqW1[DS*DS];
__device__ float g_WkW1[DS*DS];
__device__ int   g_widx[NQ*KI];
__device__ float g_w   [NQ*KI];
__device__ int   g_nidx[NQ*KN];
__device__ float g_part[256*DOUT*2];
__device__ float g_scale[DOUT];
__device__ float g_shift[DOUT];

// ---------------- generic fp32 SGEMM: C = alpha*A@B (+bias) (+C) ----------------
// M%128==0, N%128==0, K%16==0 for all call sites.
__global__ __launch_bounds__(256) void sgemm(
    const float* __restrict__ Am, const float* __restrict__ Bm,
    const float* __restrict__ bias, float* __restrict__ Cm,
    int M, int N, int K, float alpha, int useBeta, int hasBias)
{
    __shared__ float As[16*129];
    __shared__ float Bs[16*128];
    const int t  = threadIdx.x;
    const int tx = t & 15, ty = t >> 4;
    const int row0 = blockIdx.y * 128, col0 = blockIdx.x * 128;

    float acc[8][8];
#pragma unroll
    for (int i = 0; i < 8; i++)
#pragma unroll
        for (int j = 0; j < 8; j++) acc[i][j] = 0.f;

    for (int k0 = 0; k0 < K; k0 += 16) {
#pragma unroll
        for (int i = 0; i < 8; i++) {
            int L = t + i * 256;
            int r = L >> 4, kk = L & 15;
            As[kk*129 + r] = Am[(long)(row0 + r) * K + k0 + kk];
        }
#pragma unroll
        for (int i = 0; i < 8; i++) {
            int L = t + i * 256;
            int kk = L >> 7, c = L & 127;
            Bs[kk*128 + c] = Bm[(long)(k0 + kk) * N + col0 + c];
        }
        __syncthreads();
#pragma unroll
        for (int kk = 0; kk < 16; kk++) {
            float a[8], b[8];
#pragma unroll
            for (int i = 0; i < 8; i++) a[i] = As[kk*129 + ty*8 + i];
#pragma unroll
            for (int j = 0; j < 8; j++) b[j] = Bs[kk*128 + tx*8 + j];
#pragma unroll
            for (int i = 0; i < 8; i++)
#pragma unroll
                for (int j = 0; j < 8; j++)
                    acc[i][j] = fmaf(a[i], b[j], acc[i][j]);
        }
        __syncthreads();
    }
#pragma unroll
    for (int i = 0; i < 8; i++) {
        int r = row0 + ty*8 + i;
#pragma unroll
        for (int j = 0; j < 8; j++) {
            int c = col0 + tx*8 + j;
            float v = alpha * acc[i][j];
            if (hasBias) v += bias[c];
            long o = (long)r * N + c;
            if (useBeta) v += Cm[o];
            Cm[o] = v;
        }
    }
}

// ---------------- deterministic per-column BN stats ----------------
__global__ void colstats1(const float* __restrict__ X, int C, int rowsPerBlock, int R)
{
    int c = threadIdx.x, b = blockIdx.x;
    int r0 = b * rowsPerBlock, r1 = min(r0 + rowsPerBlock, R);
    float s = 0.f, s2 = 0.f;
    for (int r = r0; r < r1; r++) {
        float v = X[(long)r * C + c];
        s += v; s2 = fmaf(v, v, s2);
    }
    g_part[(b*C + c)*2]     = s;
    g_part[(b*C + c)*2 + 1] = s2;
}

__global__ void colstats2(int nb, int C, float invN,
                          const float* __restrict__ gamma, const float* __restrict__ beta)
{
    int c = threadIdx.x;
    if (c >= C) return;
    float s = 0.f, s2 = 0.f;
    for (int b = 0; b < nb; b++) {
        s  += g_part[(b*C + c)*2];
        s2 += g_part[(b*C + c)*2 + 1];
    }
    float m   = s * invN;
    float var = fmaf(-m, m, s2 * invN);
    float sc  = gamma[c] * rsqrtf(var + 1e-5f);
    g_scale[c] = sc;
    g_shift[c] = fmaf(-m, sc, beta[c]);
}

__global__ void bnrelu_inplace(float* __restrict__ X, int total, int cmask)
{
    int i = blockIdx.x * blockDim.x + threadIdx.x;
    if (i >= total) return;
    int c = i & cmask;
    float v = fmaf(X[i], g_scale[c], g_shift[c]);
    X[i] = v > 0.f ? v : 0.f;
}

// ---------------- kNN select for interpolation (top-8 of 1024, same batch) ----------------
__global__ __launch_bounds__(128) void knn_interp_sel(const float* __restrict__ p1,
                                                      const float* __restrict__ p2)
{
    __shared__ float4 sc[128];
    int q  = blockIdx.x * 128 + threadIdx.x;   // blocks never straddle batch (128 | 4096)
    int bq = q >> 12;
    int cbase = bq << 10;                       // *1024
    float qx = p1[q*3], qy = p1[q*3+1], qz = p1[q*3+2];
    float qq = qx*qx + qy*qy + qz*qz;
    float bd[KI]; int bi[KI];
#pragma unroll
    for (int k = 0; k < KI; k++) { bd[k] = 3.4e38f; bi[k] = 0; }

    for (int tile = 0; tile < N2_/128; tile++) {
        int cg = cbase + tile*128 + threadIdx.x;
        float x = p2[cg*3], y = p2[cg*3+1], z = p2[cg*3+2];
        __syncthreads();
        sc[threadIdx.x] = make_float4(x, y, z, x*x + y*y + z*z);
        __syncthreads();
        for (int jj = 0; jj < 128; jj++) {
            float4 cp = sc[jj];
            float d2 = qq + cp.w - 2.f*(qx*cp.x + qy*cp.y + qz*cp.z);
            d2 = fmaxf(d2, 0.f);
            if (d2 < bd[KI-1]) {
                float cd = d2; int ci = tile*128 + jj;
#pragma unroll
                for (int s = 0; s < KI; s++) {
                    if (cd < bd[s]) {
                        float td = bd[s]; bd[s] = cd; cd = td;
                        int   ti = bi[s]; bi[s] = ci; ci = ti;
                    }
                }
            }
        }
    }
    float rec[KI], rs = 0.f;
#pragma unroll
    for (int k = 0; k < KI; k++) { rec[k] = 1.f / (sqrtf(bd[k]) + 1e-8f); rs += rec[k]; }
    float inv = 1.f / rs;
#pragma unroll
    for (int k = 0; k < KI; k++) {
        g_widx[q*KI + k] = cbase + bi[k];
        g_w  [q*KI + k] = rec[k] * inv;
    }
}

__global__ void interp_apply(const float* __restrict__ x2)
{
    int q = blockIdx.x, c = threadIdx.x;
    float acc = 0.f;
#pragma unroll
    for (int k = 0; k < KI; k++)
        acc = fmaf(g_w[q*KI + k], x2[(long)g_widx[q*KI + k]*DS + c], acc);
    g_x2i[(long)q*DS + c] = acc;
}

// ---------------- kNN select for attention (top-16 of 4096, same batch) ----------------
__global__ __launch_bounds__(128) void knn16_sel(const float* __restrict__ p1)
{
    __shared__ float4 sc[128];
    int q  = blockIdx.x * 128 + threadIdx.x;
    int bq = q >> 12;
    int cbase = bq << 12;                       // *4096
    float qx = p1[q*3], qy = p1[q*3+1], qz = p1[q*3+2];
    float qq = qx*qx + qy*qy + qz*qz;
    float bd[KN]; int bi[KN];
#pragma unroll
    for (int k = 0; k < KN; k++) { bd[k] = 3.4e38f; bi[k] = 0; }

    for (int tile = 0; tile < N1_/128; tile++) {
        int cg = cbase + tile*128 + threadIdx.x;
        float x = p1[cg*3], y = p1[cg*3+1], z = p1[cg*3+2];
        __syncthreads();
        sc[threadIdx.x] = make_float4(x, y, z, x*x + y*y + z*z);
        __syncthreads();
        for (int jj = 0; jj < 128; jj++) {
            float4 cp = sc[jj];
            float d2 = qq + cp.w - 2.f*(qx*cp.x + qy*cp.y + qz*cp.z);
            d2 = fmaxf(d2, 0.f);
            if (d2 < bd[KN-1]) {
                float cd = d2; int ci = tile*128 + jj;
#pragma unroll
                for (int s = 0; s < KN; s++) {
                    if (cd < bd[s]) {
                        float td = bd[s]; bd[s] = cd; cd = td;
                        int   ti = bi[s]; bi[s] = ci; ci = ti;
                    }
                }
            }
        }
    }
#pragma unroll
    for (int k = 0; k < KN; k++)
        g_nidx[q*KN + k] = cbase + bi[k];
}

// ---------------- stats over virtual h = A[n] + D[idx] + b1 (262144 x 128) -------------
__global__ __launch_bounds__(128) void hstats1(const float* __restrict__ b1)
{
    int c = threadIdx.x, b = blockIdx.x;     // 256 blocks x 64 queries
    float s = 0.f, s2 = 0.f;
    for (int q = b*64; q < b*64 + 64; q++) {
        float a = g_A[(long)q*DS + c] + b1[c];
#pragma unroll 4
        for (int j = 0; j < KN; j++) {
            int row = g_nidx[q*KN + j];
            float v = a + g_Dm[(long)row*DS + c];
            s += v; s2 = fmaf(v, v, s2);
        }
    }
    g_part[(b*DS + c)*2]     = s;
    g_part[(b*DS + c)*2 + 1] = s2;
}

// ---------------- fused: build h (BN+ReLU), h@W2+b2, softmax over 16, aggregate --------
#define HS 129
__global__ __launch_bounds__(256, 1) void attn_fused(
    const float* __restrict__ b1, const float* __restrict__ W2, const float* __restrict__ b2)
{
    extern __shared__ float sh[];
    float* Hs  = sh;                     // [c][r] : Hs[c*HS + r]
    float* W2s = sh + 128*HS;            // [k][cc]: W2s[k*128 + cc]
    int*   sidx = (int*)(W2s + 128*128); // [128]

    const int t   = threadIdx.x;
    const int blk = blockIdx.x;

    if (t < 128) sidx[t] = g_nidx[blk*128 + t];
#pragma unroll 8
    for (int i = 0; i < 64; i++) {
        int L = t + i * 256;
        W2s[L] = W2[L];
    }
    __syncthreads();

#pragma unroll 4
    for (int i = 0; i < 64; i++) {
        int L = t + i * 256;
        int r = L >> 7, c = L & 127;
        int q = blk*8 + (r >> 4);
        float v = g_A[(long)q*DS + c] + g_Dm[(long)sidx[r]*DS + c] + b1[c];
        v = fmaf(v, g_scale[c], g_shift[c]);
        Hs[c*HS + r] = v > 0.f ? v : 0.f;
    }
    __syncthreads();

    const int tx = t & 15, ty = t >> 4;
    const int r0 = ty*8, c0 = tx*8;
    float acc[8][8];
#pragma unroll
    for (int i = 0; i < 8; i++)
#pragma unroll
        for (int j = 0; j < 8; j++) acc[i][j] = b2[c0 + j];

    for (int k = 0; k < 128; k++) {
        float a[8], b[8];
#pragma unroll
        for (int i = 0; i < 8; i++) a[i] = Hs[k*HS + r0 + i];
#pragma unroll
        for (int j = 0; j < 8; j++) b[j] = W2s[k*128 + c0 + j];
#pragma unroll
        for (int i = 0; i < 8; i++)
#pragma unroll
            for (int j = 0; j < 8; j++)
                acc[i][j] = fmaf(a[i], b[j], acc[i][j]);
    }

    // softmax over 16 neighbors per (query, channel): pair (ty, ty^1) via shfl.xor 16
    const int g     = ty >> 1;
    const int jbase = (ty & 1) * 8;
    const int n     = blk*8 + g;
#pragma unroll
    for (int j = 0; j < 8; j++) {
        int cc = c0 + j;
        float m = acc[0][j];
#pragma unroll
        for (int i = 1; i < 8; i++) m = fmaxf(m, acc[i][j]);
        m = fmaxf(m, __shfl_xor_sync(0xffffffffu, m, 16));
        float s = 0.f, ws = 0.f;
#pragma unroll
        for (int i = 0; i < 8; i++) {
            float e = expf(acc[i][j] - m);
            s += e;
            int row = sidx[g*16 + jbase + i];
            ws = fmaf(e, g_VX[(long)row*DS + cc], ws);
        }
        s  += __shfl_xor_sync(0xffffffffu, s,  16);
        ws += __shfl_xor_sync(0xffffffffu, ws, 16);
        if ((ty & 1) == 0) g_agg[(long)n*DS + cc] = ws / s;
    }
}

// ---------------- misc elementwise ----------------
__global__ void add_inplace(float* __restrict__ dst, const float* __restrict__ src, int total)
{
    int i = blockIdx.x * blockDim.x + threadIdx.x;
    if (i < total) dst[i] += src[i];
}

__global__ void catbuild(const float* __restrict__ x1)
{
    int i = blockIdx.x * blockDim.x + threadIdx.x;
    if (i >= NQ*DCAT) return;
    int q = i / DCAT, c = i - q*DCAT;
    g_cat[i] = (c < DS) ? g_agg[(long)q*DS + c] : x1[(long)q*DD + (c - DS)];
}

__global__ void tailwrite(const float* __restrict__ p1, const int* __restrict__ o1,
                          float* __restrict__ out, int writeO1)
{
    int i = blockIdx.x * blockDim.x + threadIdx.x;
    if (i < NQ*3) out[i] = p1[i];
    else if (writeO1 && i < NQ*3 + 4) out[NQ*3 + NQ*DOUT + (i - NQ*3)] = (float)o1[i - NQ*3];
}

// ---------------- host orchestration ----------------
static float* symf(const void* p) { return (float*)p; }

extern "C" void kernel_launch(void* const* d_in, const int* in_sizes, int n_in,
                              void* d_out, int out_size)
{
    // input layout (metadata order); handle optional batch_size scalar at idx 6
    int wi = 6;
    if (n_in >= 24 && in_sizes[6] == 1) wi = 7;
    const float* p1 = (const float*)d_in[0];
    const float* x1 = (const float*)d_in[1];
    const int*   o1 = (const int*)  d_in[2];
    const float* x2 = (const float*)d_in[4];
    const float* p2 = (const float*)d_in[3];
    const float* W_dense  = (const float*)d_in[wi + 0];
    const float* b_dense  = (const float*)d_in[wi + 1];
    const float* gd       = (const float*)d_in[wi + 2];
    const float* btd      = (const float*)d_in[wi + 3];
    const float* Wq       = (const float*)d_in[wi + 4];
    const float* Wk       = (const float*)d_in[wi + 5];
    const float* Wv       = (const float*)d_in[wi + 6];
    const float* W1       = (const float*)d_in[wi + 7];
    const float* b1       = (const float*)d_in[wi + 8];
    const float* g1       = (const float*)d_in[wi + 9];
    const float* bt1      = (const float*)d_in[wi + 10];
    const float* W2       = (const float*)d_in[wi + 11];
    const float* b2       = (const float*)d_in[wi + 12];
    const float* W_out    = (const float*)d_in[wi + 13];
    const float* b_out    = (const float*)d_in[wi + 14];
    const float* g_o      = (const float*)d_in[wi + 15];
    const float* bt_o     = (const float*)d_in[wi + 16];

    void *pxe, *px2i, *pA, *pD, *pVX, *pWqW1, *pWkW1, *pcat;
    cudaGetSymbolAddress(&pxe,  g_xe);
    cudaGetSymbolAddress(&px2i, g_x2i);
    cudaGetSymbolAddress(&pA,   g_A);
    cudaGetSymbolAddress(&pD,   g_Dm);
    cudaGetSymbolAddress(&pVX,  g_VX);
    cudaGetSymbolAddress(&pWqW1, g_WqW1);
    cudaGetSymbolAddress(&pWkW1, g_WkW1);
    cudaGetSymbolAddress(&pcat, g_cat);

    float* out = (float*)d_out;
    int full  = (out_size >= NQ*3 + NQ*DOUT + 4) ? 1 : 0;
    int pOnly = (out_size == NQ*3 + NQ*DOUT) ? 1 : 0;
    float* outx = (full || pOnly) ? (out + NQ*3) : out;

    const int shAttn = (128*HS + 128*128) * 4 + 128 * 4;
    cudaFuncSetAttribute(attn_fused, cudaFuncAttributeMaxDynamicSharedMemorySize, shAttn);

    dim3 g128(1, NQ/128);          // N=128 GEMMs over all rows
    dim3 gsmall(1, 1);
    dim3 gout(DOUT/128, NQ/128);

    // 1) dense_mlp GEMM + BN + ReLU -> x_e
    sgemm<<<g128, 256>>>(x1, W_dense, b_dense, symf(pxe), NQ, DS, DD, 1.f, 0, 1);
    colstats1<<<64, DS>>>(symf(pxe), DS, NQ/64, NQ);
    colstats2<<<1, DS>>>(64, DS, 1.f/NQ, gd, btd);
    bnrelu_inplace<<<(NQ*DS + 255)/256, 256>>>(symf(pxe), NQ*DS, DS-1);

    // 2) inverse-distance kNN interpolation -> x2i
    knn_interp_sel<<<NQ/128, 128>>>(p1, p2);
    interp_apply<<<NQ, DS>>>(x2);

    // 3) factored projections
    sgemm<<<gsmall, 256>>>(Wq, W1, nullptr, symf(pWqW1), DS, DS, DS, 1.f, 0, 0);
    sgemm<<<gsmall, 256>>>(Wk, W1, nullptr, symf(pWkW1), DS, DS, DS, 1.f, 0, 0);
    sgemm<<<g128, 256>>>(symf(pxe),  symf(pWqW1), nullptr, symf(pA), NQ, DS, DS, 1.f, 0, 0);
    sgemm<<<g128, 256>>>(symf(pxe),  W1,          nullptr, symf(pD), NQ, DS, DS, 1.f, 0, 0);
    sgemm<<<g128, 256>>>(symf(px2i), symf(pWkW1), nullptr, symf(pD), NQ, DS, DS, -1.f, 1, 0);
    sgemm<<<g128, 256>>>(symf(px2i), Wv,          nullptr, symf(pVX), NQ, DS, DS, 1.f, 0, 0);
    add_inplace<<<(NQ*DS + 255)/256, 256>>>(symf(pVX), symf(pxe), NQ*DS);

    // 4) attention neighbors + h-BN stats
    knn16_sel<<<NQ/128, 128>>>(p1);
    hstats1<<<256, DS>>>(b1);
    colstats2<<<1, DS>>>(256, DS, 1.f/(NQ*KN), g1, bt1);

    // 5) fused BN/ReLU + h@W2 + softmax + aggregate
    attn_fused<<<NQ/8, 256, shAttn>>>(b1, W2, b2);

    // 6) output mlp
    catbuild<<<(NQ*DCAT + 255)/256, 256>>>(x1);
    sgemm<<<gout, 256>>>(symf(pcat), W_out, b_out, outx, NQ, DOUT, DCAT, 1.f, 0, 1);
    colstats1<<<64, DOUT>>>(outx, DOUT, NQ/64, NQ);
    colstats2<<<1, DOUT>>>(64, DOUT, 1.f/NQ, g_o, bt_o);
    bnrelu_inplace<<<(NQ*DOUT + 255)/256, 256>>>(outx, NQ*DOUT, DOUT-1);

    // 7) tail: p1 copy + o1 as float
    if (full || pOnly)
        tailwrite<<<(NQ*3 + 4 + 255)/256, 256>>>(p1, o1, out, full);
}

// round 4
// speedup vs baseline: 1.2589x; 1.2589x over previous
#include <cuda_runtime.h>
#include <math.h>

#define NQ   16384   // B*N1
#define N1_  4096
#define N2_  1024
#define DS   128
#define DD   64
#define DCAT 192
#define DOUT 256
#define KI   8
#define KN   16

// ---------------- scratch (device globals; no allocation allowed) ----------------
__device__ float g_xe [NQ*DS];
__device__ float g_x2i[NQ*DS];
__device__ float g_A  [NQ*DS];
__device__ float g_Dm [NQ*DS];
__device__ float g_VX [NQ*DS];
__device__ float g_cat[NQ*DCAT];
__device__ float g_WqW1[DS*DS];
__device__ float g_WkW1[DS*DS];
__device__ int   g_widx[NQ*KI];
__device__ float g_w   [NQ*KI];
__device__ int   g_nidx[NQ*KN];
__device__ float g_part[256*DOUT*2];
__device__ float g_scale[DOUT];
__device__ float g_shift[DOUT];
// kNN segment partials
__device__ float g_kd16[NQ*4*KN];
__device__ int   g_ki16[NQ*4*KN];
__device__ float g_kd8 [NQ*2*KI];
__device__ int   g_ki8 [NQ*2*KI];

// ---------------- generic fp32 SGEMM: C = alpha*A@B (+bias) (+C) ----------------
// M%128==0, N%128==0, K%16==0 for all call sites.
__global__ __launch_bounds__(256) void sgemm(
    const float* __restrict__ Am, const float* __restrict__ Bm,
    const float* __restrict__ bias, float* __restrict__ Cm,
    int M, int N, int K, float alpha, int useBeta, int hasBias)
{
    __shared__ float As[16*129];
    __shared__ float Bs[16*128];
    const int t  = threadIdx.x;
    const int tx = t & 15, ty = t >> 4;
    const int row0 = blockIdx.y * 128, col0 = blockIdx.x * 128;

    float acc[8][8];
#pragma unroll
    for (int i = 0; i < 8; i++)
#pragma unroll
        for (int j = 0; j < 8; j++) acc[i][j] = 0.f;

    for (int k0 = 0; k0 < K; k0 += 16) {
#pragma unroll
        for (int i = 0; i < 8; i++) {
            int L = t + i * 256;
            int r = L >> 4, kk = L & 15;
            As[kk*129 + r] = Am[(long)(row0 + r) * K + k0 + kk];
        }
#pragma unroll
        for (int i = 0; i < 8; i++) {
            int L = t + i * 256;
            int kk = L >> 7, c = L & 127;
            Bs[kk*128 + c] = Bm[(long)(k0 + kk) * N + col0 + c];
        }
        __syncthreads();
#pragma unroll
        for (int kk = 0; kk < 16; kk++) {
            float a[8], b[8];
#pragma unroll
            for (int i = 0; i < 8; i++) a[i] = As[kk*129 + ty*8 + i];
#pragma unroll
            for (int j = 0; j < 8; j++) b[j] = Bs[kk*128 + tx*8 + j];
#pragma unroll
            for (int i = 0; i < 8; i++)
#pragma unroll
                for (int j = 0; j < 8; j++)
                    acc[i][j] = fmaf(a[i], b[j], acc[i][j]);
        }
        __syncthreads();
    }
#pragma unroll
    for (int i = 0; i < 8; i++) {
        int r = row0 + ty*8 + i;
#pragma unroll
        for (int j = 0; j < 8; j++) {
            int c = col0 + tx*8 + j;
            float v = alpha * acc[i][j];
            if (hasBias) v += bias[c];
            long o = (long)r * N + c;
            if (useBeta) v += Cm[o];
            Cm[o] = v;
        }
    }
}

// ---------------- Kahan helpers ----------------
__device__ __forceinline__ void kadd(float& s, float& cs, float v)
{
    float y = v - cs;
    float t = s + y;
    cs = (t - s) - y;
    s = t;
}

// ---------------- deterministic per-column BN stats (Kahan partials) ----------------
__global__ void colstats1(const float* __restrict__ X, int C, int rowsPerBlock, int R)
{
    int c = threadIdx.x, b = blockIdx.x;
    int r0 = b * rowsPerBlock, r1 = min(r0 + rowsPerBlock, R);
    float s = 0.f, cs = 0.f, s2 = 0.f, cs2 = 0.f;
    for (int r = r0; r < r1; r++) {
        float v = X[(long)r * C + c];
        kadd(s, cs, v);
        kadd(s2, cs2, v * v);
    }
    g_part[(b*C + c)*2]     = s;
    g_part[(b*C + c)*2 + 1] = s2;
}

__global__ void colstats2(int nb, int C, double invN,
                          const float* __restrict__ gamma, const float* __restrict__ beta)
{
    int c = threadIdx.x;
    if (c >= C) return;
    double s = 0.0, s2 = 0.0;
    for (int b = 0; b < nb; b++) {
        s  += (double)g_part[(b*C + c)*2];
        s2 += (double)g_part[(b*C + c)*2 + 1];
    }
    double m   = s * invN;
    double var = s2 * invN - m * m;
    float  sc  = gamma[c] * (float)rsqrt(var + 1e-5);
    g_scale[c] = sc;
    g_shift[c] = fmaf((float)(-m), sc, beta[c]);
}

__global__ void bnrelu4(float4* __restrict__ X, int total4, int cmask)
{
    int i = blockIdx.x * blockDim.x + threadIdx.x;
    if (i >= total4) return;
    int c = (i * 4) & cmask;
    float4 v = X[i];
    v.x = fmaf(v.x, g_scale[c+0], g_shift[c+0]);
    v.y = fmaf(v.y, g_scale[c+1], g_shift[c+1]);
    v.z = fmaf(v.z, g_scale[c+2], g_shift[c+2]);
    v.w = fmaf(v.w, g_scale[c+3], g_shift[c+3]);
    v.x = v.x > 0.f ? v.x : 0.f;
    v.y = v.y > 0.f ? v.y : 0.f;
    v.z = v.z > 0.f ? v.z : 0.f;
    v.w = v.w > 0.f ? v.w : 0.f;
    X[i] = v;
}

// ---------------- kNN partials: interpolation (top-8 per 512-candidate segment) --------
__global__ __launch_bounds__(128) void knn_interp_part(const float* __restrict__ p1,
                                                       const float* __restrict__ p2)
{
    __shared__ float4 sc[128];
    int q   = blockIdx.x * 128 + threadIdx.x;
    int seg = blockIdx.y;                       // 0..1
    int bq  = q >> 12;
    int segbase = (bq << 10) + seg * 512;
    float qx = p1[q*3], qy = p1[q*3+1], qz = p1[q*3+2];
    float qq = qx*qx + qy*qy + qz*qz;
    float bd[KI]; int bi[KI];
#pragma unroll
    for (int k = 0; k < KI; k++) { bd[k] = 3.4e38f; bi[k] = 0; }

    for (int tile = 0; tile < 4; tile++) {
        int cg = segbase + tile*128 + threadIdx.x;
        float x = p2[cg*3], y = p2[cg*3+1], z = p2[cg*3+2];
        __syncthreads();
        sc[threadIdx.x] = make_float4(x, y, z, x*x + y*y + z*z);
        __syncthreads();
        for (int jj = 0; jj < 128; jj++) {
            float4 cp = sc[jj];
            float d2 = qq + cp.w - 2.f*(qx*cp.x + qy*cp.y + qz*cp.z);
            d2 = fmaxf(d2, 0.f);
            if (d2 < bd[KI-1]) {
                float cd = d2; int ci = segbase + tile*128 + jj;
#pragma unroll
                for (int s = 0; s < KI; s++) {
                    if (cd < bd[s]) {
                        float td = bd[s]; bd[s] = cd; cd = td;
                        int   ti = bi[s]; bi[s] = ci; ci = ti;
                    }
                }
            }
        }
    }
#pragma unroll
    for (int k = 0; k < KI; k++) {
        g_kd8[(q*2 + seg)*KI + k] = bd[k];
        g_ki8[(q*2 + seg)*KI + k] = bi[k];
    }
}

__global__ void knn_interp_merge()
{
    int q = blockIdx.x * 256 + threadIdx.x;
    float bd[KI]; int bi[KI];
#pragma unroll
    for (int k = 0; k < KI; k++) { bd[k] = 3.4e38f; bi[k] = 0; }
    for (int s = 0; s < 2*KI; s++) {
        float cd = g_kd8[q*2*KI + s];
        int   ci = g_ki8[q*2*KI + s];
        if (cd < bd[KI-1]) {
#pragma unroll
            for (int k = 0; k < KI; k++) {
                if (cd < bd[k]) {
                    float td = bd[k]; bd[k] = cd; cd = td;
                    int   ti = bi[k]; bi[k] = ci; ci = ti;
                }
            }
        }
    }
    float rec[KI], rs = 0.f;
#pragma unroll
    for (int k = 0; k < KI; k++) { rec[k] = 1.f / (sqrtf(bd[k]) + 1e-8f); rs += rec[k]; }
    float inv = 1.f / rs;
#pragma unroll
    for (int k = 0; k < KI; k++) {
        g_widx[q*KI + k] = bi[k];
        g_w  [q*KI + k] = rec[k] * inv;
    }
}

__global__ void interp_apply(const float* __restrict__ x2)
{
    int q = blockIdx.x, c = threadIdx.x;
    float acc = 0.f;
#pragma unroll
    for (int k = 0; k < KI; k++)
        acc = fmaf(g_w[q*KI + k], x2[(long)g_widx[q*KI + k]*DS + c], acc);
    g_x2i[(long)q*DS + c] = acc;
}

// ---------------- kNN partials: attention (top-16 per 1024-candidate segment) ----------
__global__ __launch_bounds__(128) void knn16_part(const float* __restrict__ p1)
{
    __shared__ float4 sc[128];
    int q   = blockIdx.x * 128 + threadIdx.x;
    int seg = blockIdx.y;                       // 0..3
    int bq  = q >> 12;
    int segbase = (bq << 12) + seg * 1024;
    float qx = p1[q*3], qy = p1[q*3+1], qz = p1[q*3+2];
    float qq = qx*qx + qy*qy + qz*qz;
    float bd[KN]; int bi[KN];
#pragma unroll
    for (int k = 0; k < KN; k++) { bd[k] = 3.4e38f; bi[k] = 0; }

    for (int tile = 0; tile < 8; tile++) {
        int cg = segbase + tile*128 + threadIdx.x;
        float x = p1[cg*3], y = p1[cg*3+1], z = p1[cg*3+2];
        __syncthreads();
        sc[threadIdx.x] = make_float4(x, y, z, x*x + y*y + z*z);
        __syncthreads();
        for (int jj = 0; jj < 128; jj++) {
            float4 cp = sc[jj];
            float d2 = qq + cp.w - 2.f*(qx*cp.x + qy*cp.y + qz*cp.z);
            d2 = fmaxf(d2, 0.f);
            if (d2 < bd[KN-1]) {
                float cd = d2; int ci = segbase + tile*128 + jj;
#pragma unroll
                for (int s = 0; s < KN; s++) {
                    if (cd < bd[s]) {
                        float td = bd[s]; bd[s] = cd; cd = td;
                        int   ti = bi[s]; bi[s] = ci; ci = ti;
                    }
                }
            }
        }
    }
#pragma unroll
    for (int k = 0; k < KN; k++) {
        g_kd16[(q*4 + seg)*KN + k] = bd[k];
        g_ki16[(q*4 + seg)*KN + k] = bi[k];
    }
}

__global__ void knn16_merge()
{
    int q = blockIdx.x * 256 + threadIdx.x;
    float bd[KN]; int bi[KN];
#pragma unroll
    for (int k = 0; k < KN; k++) { bd[k] = 3.4e38f; bi[k] = 0; }
    for (int s = 0; s < 4*KN; s++) {
        float cd = g_kd16[q*4*KN + s];
        int   ci = g_ki16[q*4*KN + s];
        if (cd < bd[KN-1]) {
#pragma unroll
            for (int k = 0; k < KN; k++) {
                if (cd < bd[k]) {
                    float td = bd[k]; bd[k] = cd; cd = td;
                    int   ti = bi[k]; bi[k] = ci; ci = ti;
                }
            }
        }
    }
#pragma unroll
    for (int k = 0; k < KN; k++)
        g_nidx[q*KN + k] = bi[k];
}

// ---------------- stats over virtual h = A[n] + D[idx] + b1 (262144 x 128) -------------
__global__ __launch_bounds__(128) void hstats1(const float* __restrict__ b1)
{
    int c = threadIdx.x, b = blockIdx.x;     // 256 blocks x 64 queries
    float s = 0.f, cs = 0.f, s2 = 0.f, cs2 = 0.f;
    for (int q = b*64; q < b*64 + 64; q++) {
        float a = g_A[(long)q*DS + c] + b1[c];
#pragma unroll 4
        for (int j = 0; j < KN; j++) {
            int row = g_nidx[q*KN + j];
            float v = a + g_Dm[(long)row*DS + c];
            kadd(s, cs, v);
            kadd(s2, cs2, v * v);
        }
    }
    g_part[(b*DS + c)*2]     = s;
    g_part[(b*DS + c)*2 + 1] = s2;
}

// ---------------- fused: build h (BN+ReLU), h@W2+b2, softmax over 16, aggregate --------
#define HS 129
__global__ __launch_bounds__(256, 2) void attn_fused(
    const float* __restrict__ b1, const float* __restrict__ W2, const float* __restrict__ b2,
    float* __restrict__ cat)
{
    extern __shared__ float sh[];
    float* Hs  = sh;                      // [c][r] : Hs[c*HS + r]   (128*129)
    float* W2s = sh + 128*HS;             // [kk][cc]: 32x128 tile
    int*   sidx = (int*)(W2s + 32*128);   // [128]

    const int t   = threadIdx.x;
    const int blk = blockIdx.x;

    if (t < 128) sidx[t] = g_nidx[blk*128 + t];
    __syncthreads();

    // build Hs = relu(bn(A[n] + D[idx] + b1)), stored transposed [c][r]
#pragma unroll 4
    for (int i = 0; i < 64; i++) {
        int L = t + i * 256;
        int r = L >> 7, c = L & 127;
        int q = blk*8 + (r >> 4);
        float v = g_A[(long)q*DS + c] + g_Dm[(long)sidx[r]*DS + c] + b1[c];
        v = fmaf(v, g_scale[c], g_shift[c]);
        Hs[c*HS + r] = v > 0.f ? v : 0.f;
    }

    const int tx = t & 15, ty = t >> 4;
    const int r0 = ty*8, c0 = tx*8;
    float acc[8][8];
#pragma unroll
    for (int j = 0; j < 8; j++) {
        float bb = b2[c0 + j];
#pragma unroll
        for (int i = 0; i < 8; i++) acc[i][j] = bb;
    }

    for (int kt = 0; kt < 4; kt++) {
        __syncthreads();   // Hs done (kt=0) / previous tile's compute done (kt>0)
#pragma unroll
        for (int i = 0; i < 16; i++) {
            int L = t + i * 256;
            W2s[L] = W2[kt*4096 + L];
        }
        __syncthreads();
#pragma unroll
        for (int kk = 0; kk < 32; kk++) {
            float a[8], b[8];
            int k = kt*32 + kk;
#pragma unroll
            for (int i = 0; i < 8; i++) a[i] = Hs[k*HS + r0 + i];
#pragma unroll
            for (int j = 0; j < 8; j++) b[j] = W2s[kk*128 + c0 + j];
#pragma unroll
            for (int i = 0; i < 8; i++)
#pragma unroll
                for (int j = 0; j < 8; j++)
                    acc[i][j] = fmaf(a[i], b[j], acc[i][j]);
        }
    }

    // softmax over 16 neighbors per (query, channel): pair (ty, ty^1) via shfl.xor 16
    const int g     = ty >> 1;
    const int jbase = (ty & 1) * 8;
    const int q     = blk*8 + g;

    float m[8];
#pragma unroll
    for (int j = 0; j < 8; j++) {
        float mm = acc[0][j];
#pragma unroll
        for (int i = 1; i < 8; i++) mm = fmaxf(mm, acc[i][j]);
        mm = fmaxf(mm, __shfl_xor_sync(0xffffffffu, mm, 16));
        m[j] = mm;
    }
    float s[8], ws[8];
#pragma unroll
    for (int j = 0; j < 8; j++) { s[j] = 0.f; ws[j] = 0.f; }
#pragma unroll
    for (int i = 0; i < 8; i++) {
        int row = sidx[g*16 + jbase + i];
        const float4* vp = (const float4*)(g_VX + (long)row*DS + c0);
        float4 v0 = vp[0], v1 = vp[1];
        float e;
        e = expf(acc[i][0]-m[0]); s[0]+=e; ws[0]=fmaf(e, v0.x, ws[0]);
        e = expf(acc[i][1]-m[1]); s[1]+=e; ws[1]=fmaf(e, v0.y, ws[1]);
        e = expf(acc[i][2]-m[2]); s[2]+=e; ws[2]=fmaf(e, v0.z, ws[2]);
        e = expf(acc[i][3]-m[3]); s[3]+=e; ws[3]=fmaf(e, v0.w, ws[3]);
        e = expf(acc[i][4]-m[4]); s[4]+=e; ws[4]=fmaf(e, v1.x, ws[4]);
        e = expf(acc[i][5]-m[5]); s[5]+=e; ws[5]=fmaf(e, v1.y, ws[5]);
        e = expf(acc[i][6]-m[6]); s[6]+=e; ws[6]=fmaf(e, v1.z, ws[6]);
        e = expf(acc[i][7]-m[7]); s[7]+=e; ws[7]=fmaf(e, v1.w, ws[7]);
    }
#pragma unroll
    for (int j = 0; j < 8; j++) {
        float ss = s[j]  + __shfl_xor_sync(0xffffffffu, s[j],  16);
        float ww = ws[j] + __shfl_xor_sync(0xffffffffu, ws[j], 16);
        if ((ty & 1) == 0) cat[(long)q*DCAT + c0 + j] = ww / ss;
    }
}

// ---------------- misc elementwise ----------------
__global__ void add_inplace(float* __restrict__ dst, const float* __restrict__ src, int total)
{
    int i = blockIdx.x * blockDim.x + threadIdx.x;
    if (i < total) dst[i] += src[i];
}

__global__ void copy_x1cat(const float* __restrict__ x1)
{
    int i = blockIdx.x * blockDim.x + threadIdx.x;
    if (i >= NQ*DD) return;
    int q = i >> 6, c = i & 63;
    g_cat[(long)q*DCAT + DS + c] = x1[i];
}

__global__ void tailwrite(const float* __restrict__ p1, const int* __restrict__ o1,
                          float* __restrict__ out, int writeO1)
{
    int i = blockIdx.x * blockDim.x + threadIdx.x;
    if (i < NQ*3) out[i] = p1[i];
    else if (writeO1 && i < NQ*3 + 4) out[NQ*3 + NQ*DOUT + (i - NQ*3)] = (float)o1[i - NQ*3];
}

// ---------------- host orchestration ----------------
static float* symf(const void* p) { return (float*)p; }

extern "C" void kernel_launch(void* const* d_in, const int* in_sizes, int n_in,
                              void* d_out, int out_size)
{
    int wi = 6;
    if (n_in >= 24 && in_sizes[6] == 1) wi = 7;
    const float* p1 = (const float*)d_in[0];
    const float* x1 = (const float*)d_in[1];
    const int*   o1 = (const int*)  d_in[2];
    const float* p2 = (const float*)d_in[3];
    const float* x2 = (const float*)d_in[4];
    const float* W_dense  = (const float*)d_in[wi + 0];
    const float* b_dense  = (const float*)d_in[wi + 1];
    const float* gd       = (const float*)d_in[wi + 2];
    const float* btd      = (const float*)d_in[wi + 3];
    const float* Wq       = (const float*)d_in[wi + 4];
    const float* Wk       = (const float*)d_in[wi + 5];
    const float* Wv       = (const float*)d_in[wi + 6];
    const float* W1       = (const float*)d_in[wi + 7];
    const float* b1       = (const float*)d_in[wi + 8];
    const float* g1       = (const float*)d_in[wi + 9];
    const float* bt1      = (const float*)d_in[wi + 10];
    const float* W2       = (const float*)d_in[wi + 11];
    const float* b2       = (const float*)d_in[wi + 12];
    const float* W_out    = (const float*)d_in[wi + 13];
    const float* b_out    = (const float*)d_in[wi + 14];
    const float* g_o      = (const float*)d_in[wi + 15];
    const float* bt_o     = (const float*)d_in[wi + 16];

    void *pxe, *px2i, *pA, *pD, *pVX, *pWqW1, *pWkW1, *pcat;
    cudaGetSymbolAddress(&pxe,  g_xe);
    cudaGetSymbolAddress(&px2i, g_x2i);
    cudaGetSymbolAddress(&pA,   g_A);
    cudaGetSymbolAddress(&pD,   g_Dm);
    cudaGetSymbolAddress(&pVX,  g_VX);
    cudaGetSymbolAddress(&pWqW1, g_WqW1);
    cudaGetSymbolAddress(&pWkW1, g_WkW1);
    cudaGetSymbolAddress(&pcat, g_cat);

    float* out = (float*)d_out;
    int full  = (out_size >= NQ*3 + NQ*DOUT + 4) ? 1 : 0;
    int pOnly = (out_size == NQ*3 + NQ*DOUT) ? 1 : 0;
    float* outx = (full || pOnly) ? (out + NQ*3) : out;

    const int shAttn = (128*HS + 32*128) * 4 + 128 * 4;   // 82944 bytes
    cudaFuncSetAttribute(attn_fused, cudaFuncAttributeMaxDynamicSharedMemorySize, shAttn);

    dim3 g128(1, NQ/128);
    dim3 gsmall(1, 1);
    dim3 gout(DOUT/128, NQ/128);

    // 1) dense_mlp GEMM + BN + ReLU -> x_e
    sgemm<<<g128, 256>>>(x1, W_dense, b_dense, symf(pxe), NQ, DS, DD, 1.f, 0, 1);
    colstats1<<<64, DS>>>(symf(pxe), DS, NQ/64, NQ);
    colstats2<<<1, DS>>>(64, DS, 1.0/NQ, gd, btd);
    bnrelu4<<<(NQ*DS/4 + 255)/256, 256>>>((float4*)symf(pxe), NQ*DS/4, DS-1);

    // 2) inverse-distance kNN interpolation -> x2i
    knn_interp_part<<<dim3(NQ/128, 2), 128>>>(p1, p2);
    knn_interp_merge<<<NQ/256, 256>>>();
    interp_apply<<<NQ, DS>>>(x2);

    // 3) factored projections
    sgemm<<<gsmall, 256>>>(Wq, W1, nullptr, symf(pWqW1), DS, DS, DS, 1.f, 0, 0);
    sgemm<<<gsmall, 256>>>(Wk, W1, nullptr, symf(pWkW1), DS, DS, DS, 1.f, 0, 0);
    sgemm<<<g128, 256>>>(symf(pxe),  symf(pWqW1), nullptr, symf(pA), NQ, DS, DS, 1.f, 0, 0);
    sgemm<<<g128, 256>>>(symf(pxe),  W1,          nullptr, symf(pD), NQ, DS, DS, 1.f, 0, 0);
    sgemm<<<g128, 256>>>(symf(px2i), symf(pWkW1), nullptr, symf(pD), NQ, DS, DS, -1.f, 1, 0);
    sgemm<<<g128, 256>>>(symf(px2i), Wv,          nullptr, symf(pVX), NQ, DS, DS, 1.f, 0, 0);
    add_inplace<<<(NQ*DS + 255)/256, 256>>>(symf(pVX), symf(pxe), NQ*DS);

    // 4) attention neighbors + h-BN stats
    knn16_part<<<dim3(NQ/128, 4), 128>>>(p1);
    knn16_merge<<<NQ/256, 256>>>();
    hstats1<<<256, DS>>>(b1);
    colstats2<<<1, DS>>>(256, DS, 1.0/((double)NQ*KN), g1, bt1);

    // 5) fused BN/ReLU + h@W2 + softmax + aggregate (writes g_cat[:, :128])
    copy_x1cat<<<(NQ*DD + 255)/256, 256>>>(x1);
    attn_fused<<<NQ/8, 256, shAttn>>>(b1, W2, b2, symf(pcat));

    // 6) output mlp
    sgemm<<<gout, 256>>>(symf(pcat), W_out, b_out, outx, NQ, DOUT, DCAT, 1.f, 0, 1);
    colstats1<<<64, DOUT>>>(outx, DOUT, NQ/64, NQ);
    colstats2<<<1, DOUT>>>(64, DOUT, 1.0/NQ, g_o, bt_o);
    bnrelu4<<<(NQ*DOUT/4 + 255)/256, 256>>>((float4*)outx, NQ*DOUT/4, DOUT-1);

    // 7) tail: p1 copy + o1 as float
    if (full || pOnly)
        tailwrite<<<(NQ*3 + 4 + 255)/256, 256>>>(p1, o1, out, full);
}

// round 5
// speedup vs baseline: 1.3796x; 1.0959x over previous
#include <cuda_runtime.h>
#include <math.h>

#define NQ   16384   // B*N1
#define N1_  4096
#define N2_  1024
#define DS   128
#define DD   64
#define DCAT 192
#define DOUT 256
#define KI   8
#define KN   16

typedef unsigned long long ull;

// ---------------- scratch (device globals; no allocation allowed) ----------------
__device__ float g_xe [NQ*DS];
__device__ float g_x2i[NQ*DS];
__device__ float g_T1 [NQ*256];   // [A | Dpart]
__device__ float g_T2 [NQ*256];   // [KD | Vv]
__device__ float g_Dm [NQ*DS];
__device__ float g_VX [NQ*DS];
__device__ float g_cat[NQ*DCAT];
__device__ float g_WqW1[DS*DS];
__device__ float g_WkW1[DS*DS];
__device__ float g_Wc1[DS*256];
__device__ float g_Wc2[DS*256];
__device__ int   g_widx[NQ*KI];
__device__ float g_w   [NQ*KI];
__device__ int   g_nidx[NQ*KN];
__device__ float g_part[256*DOUT*2];
__device__ float g_scale[DOUT];
__device__ float g_shift[DOUT];
__device__ float g_kd16[NQ*4*KN];
__device__ int   g_ki16[NQ*4*KN];
__device__ float g_kd8 [NQ*2*KI];
__device__ int   g_ki8 [NQ*2*KI];

// ---------------- packed f32x2 helpers ----------------
__device__ __forceinline__ ull pack2(float x, float y)
{
    ull r;
    asm("mov.b64 %0, {%1, %2};" : "=l"(r) : "f"(x), "f"(y));
    return r;
}
__device__ __forceinline__ ull fma2(ull a, ull b, ull c)
{
    ull d;
    asm("fma.rn.f32x2 %0, %1, %2, %3;" : "=l"(d) : "l"(a), "l"(b), "l"(c));
    return d;
}
__device__ __forceinline__ float2 unpack2(ull v)
{
    float2 f;
    asm("mov.b64 {%0, %1}, %2;" : "=f"(f.x), "=f"(f.y) : "l"(v));
    return f;
}

// ---------------- fp32 SGEMM with f32x2 inner: C = alpha*A@B (+bias) ----------------
// M%128==0, N%128==0, K%16==0, K%4==0.
__global__ __launch_bounds__(256) void sgemm(
    const float* __restrict__ Am, const float* __restrict__ Bm,
    const float* __restrict__ bias, float* __restrict__ Cm,
    int M, int N, int K, float alpha, int hasBias)
{
    __shared__ __align__(16) float As[16*129];
    __shared__ __align__(16) float Bs[16*128];
    const int t  = threadIdx.x;
    const int tx = t & 15, ty = t >> 4;
    const int row0 = blockIdx.y * 128, col0 = blockIdx.x * 128;

    // A-load mapping: thread t loads rows (t>>2, +64), float4 at k-offset (t&3)*4
    const int ar = t >> 2;
    const int af = (t & 3) * 4;

    ull acc2[8][4];
#pragma unroll
    for (int i = 0; i < 8; i++)
#pragma unroll
        for (int jp = 0; jp < 4; jp++) acc2[i][jp] = pack2(0.f, 0.f);

    for (int k0 = 0; k0 < K; k0 += 16) {
#pragma unroll
        for (int h = 0; h < 2; h++) {
            int r = ar + h*64;
            float4 v = *(const float4*)&Am[(long)(row0 + r)*K + k0 + af];
            As[(af+0)*129 + r] = v.x;
            As[(af+1)*129 + r] = v.y;
            As[(af+2)*129 + r] = v.z;
            As[(af+3)*129 + r] = v.w;
        }
        {
            const float4* src = (const float4*)&Bm[(long)(k0 + ty)*N + col0 + tx*8];
            *(float4*)&Bs[ty*128 + tx*8]     = src[0];
            *(float4*)&Bs[ty*128 + tx*8 + 4] = src[1];
        }
        __syncthreads();
#pragma unroll
        for (int kk = 0; kk < 16; kk++) {
            const ull* bp = (const ull*)&Bs[kk*128 + tx*8];
            ull b0 = bp[0], b1 = bp[1], b2v = bp[2], b3 = bp[3];
            const float* ap = &As[kk*129 + ty*8];
#pragma unroll
            for (int i = 0; i < 8; i++) {
                float av = ap[i];
                ull a2 = pack2(av, av);
                acc2[i][0] = fma2(a2, b0,  acc2[i][0]);
                acc2[i][1] = fma2(a2, b1,  acc2[i][1]);
                acc2[i][2] = fma2(a2, b2v, acc2[i][2]);
                acc2[i][3] = fma2(a2, b3,  acc2[i][3]);
            }
        }
        __syncthreads();
    }
#pragma unroll
    for (int i = 0; i < 8; i++) {
        int r = row0 + ty*8 + i;
#pragma unroll
        for (int jp = 0; jp < 4; jp++) {
            int c = col0 + tx*8 + jp*2;
            float2 v = unpack2(acc2[i][jp]);
            v.x *= alpha; v.y *= alpha;
            if (hasBias) { v.x += bias[c]; v.y += bias[c+1]; }
            *(float2*)&Cm[(long)r * N + c] = v;
        }
    }
}

// ---------------- weight products: WqW1, WkW1 in one launch ----------------
__global__ __launch_bounds__(128) void wprod(const float* __restrict__ Wq,
                                             const float* __restrict__ Wk,
                                             const float* __restrict__ W1)
{
    __shared__ float row[128];
    int b = blockIdx.x;
    const float* Wsrc = (b < 128) ? Wq : Wk;
    float* dst = (b < 128) ? g_WqW1 : g_WkW1;
    int r = b & 127;
    row[threadIdx.x] = Wsrc[r*128 + threadIdx.x];
    __syncthreads();
    int c = threadIdx.x;
    float acc = 0.f;
#pragma unroll 8
    for (int k = 0; k < 128; k++) acc = fmaf(row[k], W1[k*128 + c], acc);
    dst[r*128 + c] = acc;
}

__global__ void catw(const float* __restrict__ W1, const float* __restrict__ Wv)
{
    int i = blockIdx.x * 256 + threadIdx.x;
    if (i >= 128*256) return;
    int k = i >> 8, c = i & 255;
    g_Wc1[i] = (c < 128) ? g_WqW1[k*128 + c] : W1[k*128 + c - 128];
    g_Wc2[i] = (c < 128) ? g_WkW1[k*128 + c] : Wv[k*128 + c - 128];
}

// ---------------- combine: D = T1[:,128:] - T2[:,:128]; VX = T2[:,128:] + xe -------
__global__ void combine()
{
    int i = blockIdx.x * 256 + threadIdx.x;   // over NQ*32 float4 slots
    if (i >= NQ*32) return;
    int q = i >> 5, c4 = i & 31;
    const float4* t1 = (const float4*)g_T1;
    const float4* t2 = (const float4*)g_T2;
    const float4* xe = (const float4*)g_xe;
    float4 dp = t1[q*64 + 32 + c4];
    float4 kd = t2[q*64 + c4];
    float4 vv = t2[q*64 + 32 + c4];
    float4 xv = xe[q*32 + c4];
    float4 d, v;
    d.x = dp.x - kd.x; d.y = dp.y - kd.y; d.z = dp.z - kd.z; d.w = dp.w - kd.w;
    v.x = vv.x + xv.x; v.y = vv.y + xv.y; v.z = vv.z + xv.z; v.w = vv.w + xv.w;
    ((float4*)g_Dm)[q*32 + c4] = d;
    ((float4*)g_VX)[q*32 + c4] = v;
}

// ---------------- Kahan helpers ----------------
__device__ __forceinline__ void kadd(float& s, float& cs, float v)
{
    float y = v - cs;
    float t = s + y;
    cs = (t - s) - y;
    s = t;
}

// ---------------- deterministic per-column BN stats (Kahan partials) ----------------
__global__ void colstats1(const float* __restrict__ X, int C, int rowsPerBlock, int R)
{
    int c = threadIdx.x, b = blockIdx.x;
    int r0 = b * rowsPerBlock, r1 = min(r0 + rowsPerBlock, R);
    float s = 0.f, cs = 0.f, s2 = 0.f, cs2 = 0.f;
    for (int r = r0; r < r1; r++) {
        float v = X[(long)r * C + c];
        kadd(s, cs, v);
        kadd(s2, cs2, v * v);
    }
    g_part[(b*C + c)*2]     = s;
    g_part[(b*C + c)*2 + 1] = s2;
}

__global__ void colstats2(int nb, int C, double invN,
                          const float* __restrict__ gamma, const float* __restrict__ beta)
{
    int c = threadIdx.x;
    if (c >= C) return;
    double s = 0.0, s2 = 0.0;
    for (int b = 0; b < nb; b++) {
        s  += (double)g_part[(b*C + c)*2];
        s2 += (double)g_part[(b*C + c)*2 + 1];
    }
    double m   = s * invN;
    double var = s2 * invN - m * m;
    float  sc  = gamma[c] * (float)rsqrt(var + 1e-5);
    g_scale[c] = sc;
    g_shift[c] = fmaf((float)(-m), sc, beta[c]);
}

__global__ void bnrelu4(float4* __restrict__ X, int total4, int cmask)
{
    int i = blockIdx.x * blockDim.x + threadIdx.x;
    if (i >= total4) return;
    int c = (i * 4) & cmask;
    float4 v = X[i];
    v.x = fmaf(v.x, g_scale[c+0], g_shift[c+0]);
    v.y = fmaf(v.y, g_scale[c+1], g_shift[c+1]);
    v.z = fmaf(v.z, g_scale[c+2], g_shift[c+2]);
    v.w = fmaf(v.w, g_scale[c+3], g_shift[c+3]);
    v.x = v.x > 0.f ? v.x : 0.f;
    v.y = v.y > 0.f ? v.y : 0.f;
    v.z = v.z > 0.f ? v.z : 0.f;
    v.w = v.w > 0.f ? v.w : 0.f;
    X[i] = v;
}

// ---------------- kNN partials: interpolation (top-8 per 512-candidate segment) --------
__global__ __launch_bounds__(128) void knn_interp_part(const float* __restrict__ p1,
                                                       const float* __restrict__ p2)
{
    __shared__ float4 sc[128];
    int q   = blockIdx.x * 128 + threadIdx.x;
    int seg = blockIdx.y;
    int bq  = q >> 12;
    int segbase = (bq << 10) + seg * 512;
    float qx = p1[q*3], qy = p1[q*3+1], qz = p1[q*3+2];
    float qq = qx*qx + qy*qy + qz*qz;
    float bd[KI]; int bi[KI];
#pragma unroll
    for (int k = 0; k < KI; k++) { bd[k] = 3.4e38f; bi[k] = 0; }

    for (int tile = 0; tile < 4; tile++) {
        int cg = segbase + tile*128 + threadIdx.x;
        float x = p2[cg*3], y = p2[cg*3+1], z = p2[cg*3+2];
        __syncthreads();
        sc[threadIdx.x] = make_float4(x, y, z, x*x + y*y + z*z);
        __syncthreads();
        for (int jj = 0; jj < 128; jj++) {
            float4 cp = sc[jj];
            float d2 = qq + cp.w - 2.f*(qx*cp.x + qy*cp.y + qz*cp.z);
            d2 = fmaxf(d2, 0.f);
            if (d2 < bd[KI-1]) {
                float cd = d2; int ci = segbase + tile*128 + jj;
#pragma unroll
                for (int s = 0; s < KI; s++) {
                    if (cd < bd[s]) {
                        float td = bd[s]; bd[s] = cd; cd = td;
                        int   ti = bi[s]; bi[s] = ci; ci = ti;
                    }
                }
            }
        }
    }
#pragma unroll
    for (int k = 0; k < KI; k++) {
        g_kd8[(q*2 + seg)*KI + k] = bd[k];
        g_ki8[(q*2 + seg)*KI + k] = bi[k];
    }
}

__global__ void knn_interp_merge()
{
    int q = blockIdx.x * 256 + threadIdx.x;
    float bd[KI]; int bi[KI];
#pragma unroll
    for (int k = 0; k < KI; k++) { bd[k] = 3.4e38f; bi[k] = 0; }
    for (int s = 0; s < 2*KI; s++) {
        float cd = g_kd8[q*2*KI + s];
        int   ci = g_ki8[q*2*KI + s];
        if (cd < bd[KI-1]) {
#pragma unroll
            for (int k = 0; k < KI; k++) {
                if (cd < bd[k]) {
                    float td = bd[k]; bd[k] = cd; cd = td;
                    int   ti = bi[k]; bi[k] = ci; ci = ti;
                }
            }
        }
    }
    float rec[KI], rs = 0.f;
#pragma unroll
    for (int k = 0; k < KI; k++) { rec[k] = 1.f / (sqrtf(bd[k]) + 1e-8f); rs += rec[k]; }
    float inv = 1.f / rs;
#pragma unroll
    for (int k = 0; k < KI; k++) {
        g_widx[q*KI + k] = bi[k];
        g_w  [q*KI + k] = rec[k] * inv;
    }
}

__global__ void interp_apply(const float* __restrict__ x2)
{
    int q = blockIdx.x, c = threadIdx.x;
    float acc = 0.f;
#pragma unroll
    for (int k = 0; k < KI; k++)
        acc = fmaf(g_w[q*KI + k], x2[(long)g_widx[q*KI + k]*DS + c], acc);
    g_x2i[(long)q*DS + c] = acc;
}

// ---------------- kNN partials: attention (top-16 per 1024-candidate segment) ----------
__global__ __launch_bounds__(128) void knn16_part(const float* __restrict__ p1)
{
    __shared__ float4 sc[128];
    int q   = blockIdx.x * 128 + threadIdx.x;
    int seg = blockIdx.y;
    int bq  = q >> 12;
    int segbase = (bq << 12) + seg * 1024;
    float qx = p1[q*3], qy = p1[q*3+1], qz = p1[q*3+2];
    float qq = qx*qx + qy*qy + qz*qz;
    float bd[KN]; int bi[KN];
#pragma unroll
    for (int k = 0; k < KN; k++) { bd[k] = 3.4e38f; bi[k] = 0; }

    for (int tile = 0; tile < 8; tile++) {
        int cg = segbase + tile*128 + threadIdx.x;
        float x = p1[cg*3], y = p1[cg*3+1], z = p1[cg*3+2];
        __syncthreads();
        sc[threadIdx.x] = make_float4(x, y, z, x*x + y*y + z*z);
        __syncthreads();
        for (int jj = 0; jj < 128; jj++) {
            float4 cp = sc[jj];
            float d2 = qq + cp.w - 2.f*(qx*cp.x + qy*cp.y + qz*cp.z);
            d2 = fmaxf(d2, 0.f);
            if (d2 < bd[KN-1]) {
                float cd = d2; int ci = segbase + tile*128 + jj;
#pragma unroll
                for (int s = 0; s < KN; s++) {
                    if (cd < bd[s]) {
                        float td = bd[s]; bd[s] = cd; cd = td;
                        int   ti = bi[s]; bi[s] = ci; ci = ti;
                    }
                }
            }
        }
    }
#pragma unroll
    for (int k = 0; k < KN; k++) {
        g_kd16[(q*4 + seg)*KN + k] = bd[k];
        g_ki16[(q*4 + seg)*KN + k] = bi[k];
    }
}

__global__ void knn16_merge()
{
    int q = blockIdx.x * 256 + threadIdx.x;
    float bd[KN]; int bi[KN];
#pragma unroll
    for (int k = 0; k < KN; k++) { bd[k] = 3.4e38f; bi[k] = 0; }
    for (int s = 0; s < 4*KN; s++) {
        float cd = g_kd16[q*4*KN + s];
        int   ci = g_ki16[q*4*KN + s];
        if (cd < bd[KN-1]) {
#pragma unroll
            for (int k = 0; k < KN; k++) {
                if (cd < bd[k]) {
                    float td = bd[k]; bd[k] = cd; cd = td;
                    int   ti = bi[k]; bi[k] = ci; ci = ti;
                }
            }
        }
    }
#pragma unroll
    for (int k = 0; k < KN; k++)
        g_nidx[q*KN + k] = bi[k];
}

// ---------------- stats over virtual h = A[n] + D[idx] + b1 (262144 x 128) -------------
__global__ __launch_bounds__(128) void hstats1(const float* __restrict__ b1)
{
    int c = threadIdx.x, b = blockIdx.x;     // 256 blocks x 64 queries
    float s = 0.f, cs = 0.f, s2 = 0.f, cs2 = 0.f;
    for (int q = b*64; q < b*64 + 64; q++) {
        float a = g_T1[(long)q*256 + c] + b1[c];
#pragma unroll 4
        for (int j = 0; j < KN; j++) {
            int row = g_nidx[q*KN + j];
            float v = a + g_Dm[(long)row*DS + c];
            kadd(s, cs, v);
            kadd(s2, cs2, v * v);
        }
    }
    g_part[(b*DS + c)*2]     = s;
    g_part[(b*DS + c)*2 + 1] = s2;
}

// ---------------- fused: build h (BN+ReLU), h@W2, softmax over 16, aggregate --------
#define HS 129
__global__ __launch_bounds__(256, 2) void attn_fused(
    const float* __restrict__ b1, const float* __restrict__ W2,
    float* __restrict__ cat)
{
    extern __shared__ __align__(16) float sh[];
    float* Hs  = sh;                      // [c][r]: Hs[c*HS + r] (128*129)
    float* W2s = sh + 128*HS;             // [kk][cc]: 32x128 tile
    int*   sidx = (int*)(W2s + 32*128);   // [128]

    const int t   = threadIdx.x;
    const int blk = blockIdx.x;

    if (t < 128) sidx[t] = g_nidx[blk*128 + t];
    __syncthreads();

    // build Hs = relu(bn(A[n] + D[idx] + b1)), stored transposed [c][r]
#pragma unroll 4
    for (int i = 0; i < 64; i++) {
        int L = t + i * 256;
        int r = L >> 7, c = L & 127;
        int q = blk*8 + (r >> 4);
        float v = g_T1[(long)q*256 + c] + g_Dm[(long)sidx[r]*DS + c] + b1[c];
        v = fmaf(v, g_scale[c], g_shift[c]);
        Hs[c*HS + r] = v > 0.f ? v : 0.f;
    }

    const int tx = t & 15, ty = t >> 4;
    const int r0 = ty*8, c0 = tx*8;
    ull acc2[8][4];
#pragma unroll
    for (int i = 0; i < 8; i++)
#pragma unroll
        for (int jp = 0; jp < 4; jp++) acc2[i][jp] = pack2(0.f, 0.f);

    for (int kt = 0; kt < 4; kt++) {
        __syncthreads();
#pragma unroll
        for (int i = 0; i < 16; i++) {
            int L = t + i * 256;
            W2s[L] = W2[kt*4096 + L];
        }
        __syncthreads();
#pragma unroll
        for (int kk = 0; kk < 32; kk++) {
            int k = kt*32 + kk;
            const ull* bp = (const ull*)&W2s[kk*128 + tx*8];
            ull b0 = bp[0], b1v = bp[1], b2v = bp[2], b3 = bp[3];
            const float* ap = &Hs[k*HS + r0];
#pragma unroll
            for (int i = 0; i < 8; i++) {
                float av = ap[i];
                ull a2 = pack2(av, av);
                acc2[i][0] = fma2(a2, b0,  acc2[i][0]);
                acc2[i][1] = fma2(a2, b1v, acc2[i][1]);
                acc2[i][2] = fma2(a2, b2v, acc2[i][2]);
                acc2[i][3] = fma2(a2, b3,  acc2[i][3]);
            }
        }
    }

    // unpack (b2 omitted: constant per channel across the softmax axis -> cancels)
    float acc[8][8];
#pragma unroll
    for (int i = 0; i < 8; i++)
#pragma unroll
        for (int jp = 0; jp < 4; jp++) {
            float2 v = unpack2(acc2[i][jp]);
            acc[i][jp*2]     = v.x;
            acc[i][jp*2 + 1] = v.y;
        }

    // softmax over 16 neighbors per (query, channel): pair (ty, ty^1) via shfl.xor 16
    const int g     = ty >> 1;
    const int jbase = (ty & 1) * 8;
    const int q     = blk*8 + g;

    float m[8];
#pragma unroll
    for (int j = 0; j < 8; j++) {
        float mm = acc[0][j];
#pragma unroll
        for (int i = 1; i < 8; i++) mm = fmaxf(mm, acc[i][j]);
        mm = fmaxf(mm, __shfl_xor_sync(0xffffffffu, mm, 16));
        m[j] = mm;
    }
    float s[8], ws[8];
#pragma unroll
    for (int j = 0; j < 8; j++) { s[j] = 0.f; ws[j] = 0.f; }
#pragma unroll
    for (int i = 0; i < 8; i++) {
        int row = sidx[g*16 + jbase + i];
        const float4* vp = (const float4*)(g_VX + (long)row*DS + c0);
        float4 v0 = vp[0], v1 = vp[1];
        float e;
        e = expf(acc[i][0]-m[0]); s[0]+=e; ws[0]=fmaf(e, v0.x, ws[0]);
        e = expf(acc[i][1]-m[1]); s[1]+=e; ws[1]=fmaf(e, v0.y, ws[1]);
        e = expf(acc[i][2]-m[2]); s[2]+=e; ws[2]=fmaf(e, v0.z, ws[2]);
        e = expf(acc[i][3]-m[3]); s[3]+=e; ws[3]=fmaf(e, v0.w, ws[3]);
        e = expf(acc[i][4]-m[4]); s[4]+=e; ws[4]=fmaf(e, v1.x, ws[4]);
        e = expf(acc[i][5]-m[5]); s[5]+=e; ws[5]=fmaf(e, v1.y, ws[5]);
        e = expf(acc[i][6]-m[6]); s[6]+=e; ws[6]=fmaf(e, v1.z, ws[6]);
        e = expf(acc[i][7]-m[7]); s[7]+=e; ws[7]=fmaf(e, v1.w, ws[7]);
    }
#pragma unroll
    for (int j = 0; j < 8; j++) {
        float ss = s[j]  + __shfl_xor_sync(0xffffffffu, s[j],  16);
        float ww = ws[j] + __shfl_xor_sync(0xffffffffu, ws[j], 16);
        if ((ty & 1) == 0) cat[(long)q*DCAT + c0 + j] = ww / ss;
    }
}

// ---------------- misc elementwise ----------------
__global__ void copy_x1cat(const float* __restrict__ x1)
{
    int i = blockIdx.x * blockDim.x + threadIdx.x;
    if (i >= NQ*DD) return;
    int q = i >> 6, c = i & 63;
    g_cat[(long)q*DCAT + DS + c] = x1[i];
}

__global__ void tailwrite(const float* __restrict__ p1, const int* __restrict__ o1,
                          float* __restrict__ out, int writeO1)
{
    int i = blockIdx.x * blockDim.x + threadIdx.x;
    if (i < NQ*3) out[i] = p1[i];
    else if (writeO1 && i < NQ*3 + 4) out[NQ*3 + NQ*DOUT + (i - NQ*3)] = (float)o1[i - NQ*3];
}

// ---------------- host orchestration ----------------
static float* symf(const void* p) { return (float*)p; }

extern "C" void kernel_launch(void* const* d_in, const int* in_sizes, int n_in,
                              void* d_out, int out_size)
{
    int wi = 6;
    if (n_in >= 24 && in_sizes[6] == 1) wi = 7;
    const float* p1 = (const float*)d_in[0];
    const float* x1 = (const float*)d_in[1];
    const int*   o1 = (const int*)  d_in[2];
    const float* p2 = (const float*)d_in[3];
    const float* x2 = (const float*)d_in[4];
    const float* W_dense  = (const float*)d_in[wi + 0];
    const float* b_dense  = (const float*)d_in[wi + 1];
    const float* gd       = (const float*)d_in[wi + 2];
    const float* btd      = (const float*)d_in[wi + 3];
    const float* Wq       = (const float*)d_in[wi + 4];
    const float* Wk       = (const float*)d_in[wi + 5];
    const float* Wv       = (const float*)d_in[wi + 6];
    const float* W1       = (const float*)d_in[wi + 7];
    const float* b1       = (const float*)d_in[wi + 8];
    const float* g1       = (const float*)d_in[wi + 9];
    const float* bt1      = (const float*)d_in[wi + 10];
    const float* W2       = (const float*)d_in[wi + 11];
    const float* W_out    = (const float*)d_in[wi + 13];
    const float* b_out    = (const float*)d_in[wi + 14];
    const float* g_o      = (const float*)d_in[wi + 15];
    const float* bt_o     = (const float*)d_in[wi + 16];

    void *pxe, *px2i, *pT1, *pT2, *pWc1, *pWc2, *pcat;
    cudaGetSymbolAddress(&pxe,  g_xe);
    cudaGetSymbolAddress(&px2i, g_x2i);
    cudaGetSymbolAddress(&pT1,  g_T1);
    cudaGetSymbolAddress(&pT2,  g_T2);
    cudaGetSymbolAddress(&pWc1, g_Wc1);
    cudaGetSymbolAddress(&pWc2, g_Wc2);
    cudaGetSymbolAddress(&pcat, g_cat);

    float* out = (float*)d_out;
    int full  = (out_size >= NQ*3 + NQ*DOUT + 4) ? 1 : 0;
    int pOnly = (out_size == NQ*3 + NQ*DOUT) ? 1 : 0;
    float* outx = (full || pOnly) ? (out + NQ*3) : out;

    const int shAttn = (128*HS + 32*128) * 4 + 128 * 4;
    cudaFuncSetAttribute(attn_fused, cudaFuncAttributeMaxDynamicSharedMemorySize, shAttn);

    dim3 g128(1, NQ/128);
    dim3 g256(2, NQ/128);

    // 0) weight precompute (no data deps)
    wprod<<<256, 128>>>(Wq, Wk, W1);
    catw<<<128, 256>>>(W1, Wv);

    // 1) dense_mlp GEMM + BN + ReLU -> x_e
    sgemm<<<g128, 256>>>(x1, W_dense, b_dense, symf(pxe), NQ, DS, DD, 1.f, 1);
    colstats1<<<64, DS>>>(symf(pxe), DS, NQ/64, NQ);
    colstats2<<<1, DS>>>(64, DS, 1.0/NQ, gd, btd);
    bnrelu4<<<(NQ*DS/4 + 255)/256, 256>>>((float4*)symf(pxe), NQ*DS/4, DS-1);

    // 2) inverse-distance kNN interpolation -> x2i
    knn_interp_part<<<dim3(NQ/128, 2), 128>>>(p1, p2);
    knn_interp_merge<<<NQ/256, 256>>>();
    interp_apply<<<NQ, DS>>>(x2);

    // 3) fused projections: T1 = xe@[WqW1|W1], T2 = x2i@[WkW1|Wv]; then combine
    sgemm<<<g256, 256>>>(symf(pxe),  symf(pWc1), nullptr, symf(pT1), NQ, 256, DS, 1.f, 0);
    sgemm<<<g256, 256>>>(symf(px2i), symf(pWc2), nullptr, symf(pT2), NQ, 256, DS, 1.f, 0);
    combine<<<(NQ*32 + 255)/256, 256>>>();

    // 4) attention neighbors + h-BN stats
    knn16_part<<<dim3(NQ/128, 4), 128>>>(p1);
    knn16_merge<<<NQ/256, 256>>>();
    hstats1<<<256, DS>>>(b1);
    colstats2<<<1, DS>>>(256, DS, 1.0/((double)NQ*KN), g1, bt1);

    // 5) fused BN/ReLU + h@W2 + softmax + aggregate (writes g_cat[:, :128])
    copy_x1cat<<<(NQ*DD + 255)/256, 256>>>(x1);
    attn_fused<<<NQ/8, 256, shAttn>>>(b1, W2, symf(pcat));

    // 6) output mlp
    sgemm<<<g256, 256>>>(symf(pcat), W_out, b_out, outx, NQ, DOUT, DCAT, 1.f, 1);
    colstats1<<<64, DOUT>>>(outx, DOUT, NQ/64, NQ);
    colstats2<<<1, DOUT>>>(64, DOUT, 1.0/NQ, g_o, bt_o);
    bnrelu4<<<(NQ*DOUT/4 + 255)/256, 256>>>((float4*)outx, NQ*DOUT/4, DOUT-1);

    // 7) tail: p1 copy + o1 as float
    if (full || pOnly)
        tailwrite<<<(NQ*3 + 4 + 255)/256, 256>>>(p1, o1, out, full);
}